// round 9
// baseline (speedup 1.0000x reference)
#include <cuda_runtime.h>
#include <cuda_bf16.h>
#include <cstdint>

// ---------------- problem constants ----------------
#define BATCH 4
#define SEQ   4096
#define DIM   1024
#define HEADS 16
#define DHEAD 64
#define INNER 1024
#define MROWS (BATCH*SEQ)   // 16384
#define QKVN  (3*INNER)     // 3072
#define LN_EPS 1e-5f

// ---------------- scratch (device globals; no allocs allowed) ----------------
__device__ float g_kvp[64*8*64*64];            // kv split partials (fp32)
__device__ float g_o[MROWS*INNER];             // attention out (fp32), LN reads

// bf16 hi/lo operand storage
__device__ __nv_bfloat16 g_xhi[MROWS*DIM];     // A of GEMM1 (x) and GEMM2 (LN out)
__device__ __nv_bfloat16 g_xlo[MROWS*DIM];
__device__ __nv_bfloat16 g_w1hi[QKVN*DIM];     // w_qkv^T [N][K]
__device__ __nv_bfloat16 g_w1lo[QKVN*DIM];
__device__ __nv_bfloat16 g_w2hi[DIM*DIM];      // w_out^T [N][K]
__device__ __nv_bfloat16 g_w2lo[DIM*DIM];
__device__ __nv_bfloat16 g_qh[BATCH*HEADS*SEQ*DHEAD];
__device__ __nv_bfloat16 g_ql[BATCH*HEADS*SEQ*DHEAD];
__device__ __nv_bfloat16 g_kh[BATCH*HEADS*SEQ*DHEAD];
__device__ __nv_bfloat16 g_kl[BATCH*HEADS*SEQ*DHEAD];
__device__ __nv_bfloat16 g_vh[BATCH*HEADS*SEQ*DHEAD];
__device__ __nv_bfloat16 g_vl[BATCH*HEADS*SEQ*DHEAD];
__device__ __nv_bfloat16 g_kvth[64*64*64];     // kv^T hi/lo  [bh][d][m]
__device__ __nv_bfloat16 g_kvtl[64*64*64];

// =====================================================================
// helpers
// =====================================================================
__device__ __forceinline__ uint32_t smem_u32(const void* p) {
    uint32_t a;
    asm("{ .reg .u64 t; cvta.to.shared.u64 t, %1; cvt.u32.u64 %0, t; }"
        : "=r"(a) : "l"(p));
    return a;
}

__device__ __forceinline__ void cpa16(uint32_t s, const void* g) {
    asm volatile("cp.async.cg.shared.global [%0], [%1], 16;"
                 :: "r"(s), "l"(__cvta_generic_to_global(g)) : "memory");
}
#define CP_COMMIT() asm volatile("cp.async.commit_group;" ::: "memory")
#define CP_WAIT(n)  asm volatile("cp.async.wait_group %0;" :: "n"(n) : "memory")

__device__ __forceinline__ void ldm_x4(uint32_t addr, uint32_t* r) {
    asm volatile("ldmatrix.sync.aligned.m8n8.x4.shared.b16 {%0,%1,%2,%3}, [%4];"
        : "=r"(r[0]), "=r"(r[1]), "=r"(r[2]), "=r"(r[3]) : "r"(addr));
}

__device__ __forceinline__ void mma16816(float* d, const uint32_t* a, const uint32_t* b) {
    asm volatile("mma.sync.aligned.m16n8k16.row.col.f32.bf16.bf16.f32 "
        "{%0,%1,%2,%3}, {%4,%5,%6,%7}, {%8,%9}, {%0,%1,%2,%3};"
        : "+f"(d[0]), "+f"(d[1]), "+f"(d[2]), "+f"(d[3])
        : "r"(a[0]), "r"(a[1]), "r"(a[2]), "r"(a[3]), "r"(b[0]), "r"(b[1]));
}

__device__ __forceinline__ void split1(float f, __nv_bfloat16& h, __nv_bfloat16& l) {
    h = __float2bfloat16(f);
    l = __float2bfloat16(f - __bfloat162float(h));
}

__device__ __forceinline__ uint32_t pack2(__nv_bfloat16 a, __nv_bfloat16 b) {
    __nv_bfloat162 t = __halves2bfloat162(a, b);
    return *reinterpret_cast<uint32_t*>(&t);
}

// =====================================================================
// conversion kernels
// =====================================================================
__global__ __launch_bounds__(256)
void cvt_split(const float* __restrict__ in)
{
    long i = (long)blockIdx.x*256 + threadIdx.x;
    float4 v = ((const float4*)in)[i];
    __nv_bfloat16 h0,h1,h2,h3,l0,l1,l2,l3;
    split1(v.x,h0,l0); split1(v.y,h1,l1); split1(v.z,h2,l2); split1(v.w,h3,l3);
    ((uint2*)g_xhi)[i] = make_uint2(pack2(h0,h1), pack2(h2,h3));
    ((uint2*)g_xlo)[i] = make_uint2(pack2(l0,l1), pack2(l2,l3));
}

__global__ __launch_bounds__(256)
void cvt_split_trans(const float* __restrict__ in, int N, int sel)
{
    __shared__ float t[32][33];
    const int n0 = blockIdx.x*32, k0 = blockIdx.y*32;
    const int tid = threadIdx.x;
    __nv_bfloat16* hi = sel ? g_w2hi : g_w1hi;
    __nv_bfloat16* lo = sel ? g_w2lo : g_w1lo;

    #pragma unroll
    for (int i = 0; i < 4; i++) {
        int r = (tid >> 5) + i*8, c = tid & 31;
        t[r][c] = in[(long)(k0+r)*N + n0 + c];
    }
    __syncthreads();
    #pragma unroll
    for (int i = 0; i < 4; i++) {
        int a = (tid >> 5) + i*8;
        int b = tid & 31;
        float f = t[b][a];
        __nv_bfloat16 h, l;
        split1(f, h, l);
        hi[(long)(n0+a)*DIM + k0 + b] = h;
        lo[(long)(n0+a)*DIM + k0 + b] = l;
    }
}

// =====================================================================
// bf16x3 mma.sync GEMM (unchanged from R8): CTA 128x128, warp 64x32,
//   K-chunk 64, 3-stage cp.async, term-outermost MMA order
// =====================================================================
#define ST_AHI 0
#define ST_ALO 16384
#define ST_BHI 32768
#define ST_BLO 49152
#define ST_SZ  65536
#define GEMM_SMEM (3*ST_SZ)

__global__ __launch_bounds__(256, 1)
void mma_gemm(const float* __restrict__ bias, float* __restrict__ Cout, int mode)
{
    extern __shared__ char smem[];
    const uint32_t sb = smem_u32(smem);
    const int tid  = threadIdx.x;
    const int lane = tid & 31, wid = tid >> 5;
    const int wm = wid >> 2, wn = wid & 3;          // 2 x 4 warps, 64x32 each
    const int m0 = blockIdx.y * 128;
    const int n0 = blockIdx.x * 128;

    const __nv_bfloat16* Ahi = g_xhi;
    const __nv_bfloat16* Alo = g_xlo;
    const __nv_bfloat16* Bhi = mode ? g_w2hi : g_w1hi;
    const __nv_bfloat16* Blo = mode ? g_w2lo : g_w1lo;

    auto issue = [&](int chunk, int buf) {
        const uint32_t so = sb + buf*ST_SZ;
        const int kofs = chunk * 64;
        #pragma unroll
        for (int i = 0; i < 4; i++) {
            int cid = tid + i*256;
            int row = cid >> 3, c16 = cid & 7;
            uint32_t off = row*128 + c16*16;
            uint32_t sw = off ^ ((off >> 3) & 0x70);
            long ga = (long)(m0 + row)*DIM + kofs + c16*8;
            long gb = (long)(n0 + row)*DIM + kofs + c16*8;
            cpa16(so + ST_AHI + sw, Ahi + ga);
            cpa16(so + ST_ALO + sw, Alo + ga);
            cpa16(so + ST_BHI + sw, Bhi + gb);
            cpa16(so + ST_BLO + sw, Blo + gb);
        }
        CP_COMMIT();
    };

    const int ra  = lane & 15;
    const int kba = ((lane >> 4) & 1) * 16;
    const int nnb = (lane & 7) + ((lane >> 4) & 1)*8;
    const int kbb = ((lane >> 3) & 1) * 16;

    float acc[4][4][4];
    #pragma unroll
    for (int a = 0; a < 4; a++)
        #pragma unroll
        for (int b = 0; b < 4; b++)
            #pragma unroll
            for (int d = 0; d < 4; d++) acc[a][b][d] = 0.f;

    issue(0, 0); issue(1, 1);

    int buf = 0, nbuf = 2;
    #pragma unroll 1
    for (int c = 0; c < 16; c++) {
        if (c < 15) { CP_WAIT(1); } else { CP_WAIT(0); }
        __syncthreads();
        if (c + 2 < 16) issue(c + 2, nbuf);

        const uint32_t so = sb + buf*ST_SZ;

        #pragma unroll
        for (int k16 = 0; k16 < 4; k16++) {
            uint32_t ah[4][4], al[4][4], bh2[2][4], bl2[2][4];
            {
                const int ka = k16*32 + kba;
                #pragma unroll
                for (int mf = 0; mf < 4; mf++) {
                    uint32_t off = (uint32_t)(wm*64 + mf*16 + ra)*128 + ka;
                    uint32_t sw = off ^ ((off >> 3) & 0x70);
                    ldm_x4(so + ST_AHI + sw, ah[mf]);
                    ldm_x4(so + ST_ALO + sw, al[mf]);
                }
            }
            {
                const int kb = k16*32 + kbb;
                #pragma unroll
                for (int np = 0; np < 2; np++) {
                    uint32_t off = (uint32_t)(wn*32 + np*16 + nnb)*128 + kb;
                    uint32_t sw = off ^ ((off >> 3) & 0x70);
                    ldm_x4(so + ST_BHI + sw, bh2[np]);
                    ldm_x4(so + ST_BLO + sw, bl2[np]);
                }
            }
            #pragma unroll
            for (int mf = 0; mf < 4; mf++)
                #pragma unroll
                for (int nf = 0; nf < 4; nf++)
                    mma16816(acc[mf][nf], ah[mf], &bh2[nf >> 1][(nf & 1)*2]);
            #pragma unroll
            for (int mf = 0; mf < 4; mf++)
                #pragma unroll
                for (int nf = 0; nf < 4; nf++)
                    mma16816(acc[mf][nf], ah[mf], &bl2[nf >> 1][(nf & 1)*2]);
            #pragma unroll
            for (int mf = 0; mf < 4; mf++)
                #pragma unroll
                for (int nf = 0; nf < 4; nf++)
                    mma16816(acc[mf][nf], al[mf], &bh2[nf >> 1][(nf & 1)*2]);
        }
        buf = (buf == 2) ? 0 : buf + 1;
        nbuf = (nbuf == 2) ? 0 : nbuf + 1;
    }
    __syncthreads();

    // ---- epilogue: stage fp32 in smem, coalesced out ----
    float* stg = (float*)smem;                      // [128][132]
    #pragma unroll
    for (int mf = 0; mf < 4; mf++)
        #pragma unroll
        for (int nf = 0; nf < 4; nf++) {
            int row = wm*64 + mf*16 + (lane >> 2);
            int col = wn*32 + nf*8 + (lane & 3)*2;
            stg[row*132 + col]       = acc[mf][nf][0];
            stg[row*132 + col + 1]   = acc[mf][nf][1];
            stg[(row+8)*132 + col]   = acc[mf][nf][2];
            stg[(row+8)*132 + col+1] = acc[mf][nf][3];
        }
    __syncthreads();

    #pragma unroll 1
    for (int i = 0; i < 16; i++) {
        int slot = tid + i*256;
        int row = slot >> 5, c4 = slot & 31;
        float4 v = *(const float4*)&stg[row*132 + c4*4];
        int gm = m0 + row;
        int gn = n0 + c4*4;
        if (mode == 0) {
            int part = gn >> 10;
            int inner = gn & 1023;
            int h = inner >> 6, d = inner & 63;
            int b = gm >> 12, s = gm & 4095;
            long dst = (((long)(b*16 + h))*4096 + s)*64 + d;
            if (part != 2) {
                v.x = fmaxf(v.x, 0.f); v.y = fmaxf(v.y, 0.f);
                v.z = fmaxf(v.z, 0.f); v.w = fmaxf(v.w, 0.f);
            }
            __nv_bfloat16 h0,h1,h2,h3,l0,l1,l2,l3;
            split1(v.x,h0,l0); split1(v.y,h1,l1); split1(v.z,h2,l2); split1(v.w,h3,l3);
            uint2 uh = make_uint2(pack2(h0,h1), pack2(h2,h3));
            uint2 ul = make_uint2(pack2(l0,l1), pack2(l2,l3));
            if (part == 0)      { *(uint2*)(g_qh+dst) = uh; *(uint2*)(g_ql+dst) = ul; }
            else if (part == 1) { *(uint2*)(g_kh+dst) = uh; *(uint2*)(g_kl+dst) = ul; }
            else                { *(uint2*)(g_vh+dst) = uh; *(uint2*)(g_vl+dst) = ul; }
        } else {
            float4 bs = *(const float4*)(bias + gn);
            v.x += bs.x; v.y += bs.y; v.z += bs.z; v.w += bs.w;
            *(float4*)(Cout + (long)gm*DIM + gn) = v;
        }
    }
}

// =====================================================================
// kv partials on the TENSOR pipe: kvp[d][e] = sum_n k[n][d] * v[n][e]
//   Per (bh,split) block: 512 seq rows, staged transposed into padded
//   smem ([d][n], stride 72 elems -> conflict-free ldmatrix rows),
//   3-term bf16 MMA with the same fragment addressing as mma_gemm.
// =====================================================================
#define KVP_STRIDE 72   // elements; 144B row stride -> +4 banks per row

__global__ __launch_bounds__(256)
void kv_partial()
{
    __shared__ __nv_bfloat16 sKh[64*KVP_STRIDE];
    __shared__ __nv_bfloat16 sKl[64*KVP_STRIDE];
    __shared__ __nv_bfloat16 sVh[64*KVP_STRIDE];
    __shared__ __nv_bfloat16 sVl[64*KVP_STRIDE];

    const int bh = blockIdx.x >> 3;
    const int split = blockIdx.x & 7;
    const int tid = threadIdx.x;
    const int lane = tid & 31, wid = tid >> 5;
    const int wm2 = wid >> 1;          // 0..3  (m = d1, 16 rows each)
    const int wn2 = wid & 1;           // 0..1  (n = d2, 32 cols each)

    const uint32_t bKh = smem_u32(sKh);
    const uint32_t bKl = smem_u32(sKl);
    const uint32_t bVh = smem_u32(sVh);
    const uint32_t bVl = smem_u32(sVl);

    const long base = ((long)bh*SEQ + split*512)*DHEAD;

    const int ra  = lane & 15;
    const int kba = ((lane >> 4) & 1) * 16;        // bytes
    const int nnb = (lane & 7) + ((lane >> 4) & 1)*8;
    const int kbb = ((lane >> 3) & 1) * 16;        // bytes

    float acc[4][4];
    #pragma unroll
    for (int i = 0; i < 4; i++)
        #pragma unroll
        for (int j = 0; j < 4; j++) acc[i][j] = 0.f;

    #pragma unroll 1
    for (int s = 0; s < 8; s++) {
        const long nb = base + (long)(s*64)*DHEAD;
        // stage 64 seq-rows transposed: smem[d][n] = gmem[n][d]
        #pragma unroll
        for (int it = 0; it < 4; it++) {
            int cid = tid + it*256;            // 1024 slots: 64 n x 16 d-chunks
            int n  = cid >> 4;
            int dc = (cid & 15) * 4;
            long ga = nb + (long)n*DHEAD + dc;
            uint2 ukh = *(const uint2*)(g_kh + ga);
            uint2 ukl = *(const uint2*)(g_kl + ga);
            uint2 uvh = *(const uint2*)(g_vh + ga);
            uint2 uvl = *(const uint2*)(g_vl + ga);
            __nv_bfloat162 kh0 = *reinterpret_cast<__nv_bfloat162*>(&ukh.x);
            __nv_bfloat162 kh1 = *reinterpret_cast<__nv_bfloat162*>(&ukh.y);
            __nv_bfloat162 kl0 = *reinterpret_cast<__nv_bfloat162*>(&ukl.x);
            __nv_bfloat162 kl1 = *reinterpret_cast<__nv_bfloat162*>(&ukl.y);
            __nv_bfloat162 vh0 = *reinterpret_cast<__nv_bfloat162*>(&uvh.x);
            __nv_bfloat162 vh1 = *reinterpret_cast<__nv_bfloat162*>(&uvh.y);
            __nv_bfloat162 vl0 = *reinterpret_cast<__nv_bfloat162*>(&uvl.x);
            __nv_bfloat162 vl1 = *reinterpret_cast<__nv_bfloat162*>(&uvl.y);
            sKh[(dc+0)*KVP_STRIDE + n] = __low2bfloat16(kh0);
            sKh[(dc+1)*KVP_STRIDE + n] = __high2bfloat16(kh0);
            sKh[(dc+2)*KVP_STRIDE + n] = __low2bfloat16(kh1);
            sKh[(dc+3)*KVP_STRIDE + n] = __high2bfloat16(kh1);
            sKl[(dc+0)*KVP_STRIDE + n] = __low2bfloat16(kl0);
            sKl[(dc+1)*KVP_STRIDE + n] = __high2bfloat16(kl0);
            sKl[(dc+2)*KVP_STRIDE + n] = __low2bfloat16(kl1);
            sKl[(dc+3)*KVP_STRIDE + n] = __high2bfloat16(kl1);
            sVh[(dc+0)*KVP_STRIDE + n] = __low2bfloat16(vh0);
            sVh[(dc+1)*KVP_STRIDE + n] = __high2bfloat16(vh0);
            sVh[(dc+2)*KVP_STRIDE + n] = __low2bfloat16(vh1);
            sVh[(dc+3)*KVP_STRIDE + n] = __high2bfloat16(vh1);
            sVl[(dc+0)*KVP_STRIDE + n] = __low2bfloat16(vl0);
            sVl[(dc+1)*KVP_STRIDE + n] = __high2bfloat16(vl0);
            sVl[(dc+2)*KVP_STRIDE + n] = __low2bfloat16(vl1);
            sVl[(dc+3)*KVP_STRIDE + n] = __high2bfloat16(vl1);
        }
        __syncthreads();

        #pragma unroll
        for (int k16 = 0; k16 < 4; k16++) {
            uint32_t ah[4], al[4], bh2[2][4], bl2[2][4];
            {
                uint32_t off = (uint32_t)(wm2*16 + ra)*(KVP_STRIDE*2) + k16*32 + kba;
                ldm_x4(bKh + off, ah);
                ldm_x4(bKl + off, al);
            }
            #pragma unroll
            for (int np = 0; np < 2; np++) {
                uint32_t off = (uint32_t)(wn2*32 + np*16 + nnb)*(KVP_STRIDE*2) + k16*32 + kbb;
                ldm_x4(bVh + off, bh2[np]);
                ldm_x4(bVl + off, bl2[np]);
            }
            #pragma unroll
            for (int nf = 0; nf < 4; nf++)
                mma16816(acc[nf], ah, &bh2[nf >> 1][(nf & 1)*2]);
            #pragma unroll
            for (int nf = 0; nf < 4; nf++)
                mma16816(acc[nf], ah, &bl2[nf >> 1][(nf & 1)*2]);
            #pragma unroll
            for (int nf = 0; nf < 4; nf++)
                mma16816(acc[nf], al, &bh2[nf >> 1][(nf & 1)*2]);
        }
        __syncthreads();
    }

    float* dst = g_kvp + (long)blockIdx.x*4096;
    #pragma unroll
    for (int nf = 0; nf < 4; nf++) {
        int row = wm2*16 + (lane >> 2);
        int col = wn2*32 + nf*8 + (lane & 3)*2;
        dst[row*64 + col]       = acc[nf][0];
        dst[row*64 + col + 1]   = acc[nf][1];
        dst[(row+8)*64 + col]   = acc[nf][2];
        dst[(row+8)*64 + col+1] = acc[nf][3];
    }
}

__global__ void kv_reduce()
{
    int idx = blockIdx.x*256 + threadIdx.x;
    int bh = idx >> 12;
    int rem = idx & 4095;
    int m = rem >> 6, d = rem & 63;
    float s = 0.f;
    #pragma unroll
    for (int sp = 0; sp < 8; sp++)
        s += g_kvp[((long)(bh*8 + sp))*4096 + rem];
    __nv_bfloat16 h, l;
    split1(s, h, l);
    g_kvth[(long)bh*4096 + d*64 + m] = h;
    g_kvtl[(long)bh*4096 + d*64 + m] = l;
}

// =====================================================================
// o = q @ kv per (b,h): bf16x3 MMA, M=128 N=64 K=64 (unchanged)
// =====================================================================
#define OS_QHI 0
#define OS_QLO 16384
#define OS_BHI 32768
#define OS_BLO 40960

__global__ __launch_bounds__(256)
void o_mma()
{
    __shared__ char sm[49152];
    const uint32_t sb = smem_u32(sm);
    const int tid = threadIdx.x;
    const int lane = tid & 31, wm = tid >> 5;       // 8 warps x (16m x 64n)
    const int bh = blockIdx.x >> 5;
    const int mt = blockIdx.x & 31;
    const int b = bh >> 4, h = bh & 15;

    const long qbase = ((long)bh*SEQ + mt*128)*DHEAD;
    #pragma unroll
    for (int i = 0; i < 4; i++) {
        int cid = tid + i*256;
        int row = cid >> 3, c16 = cid & 7;
        uint32_t off = row*128 + c16*16;
        uint32_t sw = off ^ ((off >> 3) & 0x70);
        long ga = qbase + (long)row*DHEAD + c16*8;
        cpa16(sb + OS_QHI + sw, g_qh + ga);
        cpa16(sb + OS_QLO + sw, g_ql + ga);
    }
    #pragma unroll
    for (int i = 0; i < 2; i++) {
        int cid = tid + i*256;
        int row = cid >> 3, c16 = cid & 7;
        uint32_t off = row*128 + c16*16;
        uint32_t sw = off ^ ((off >> 3) & 0x70);
        long gb = (long)bh*4096 + row*64 + c16*8;
        cpa16(sb + OS_BHI + sw, g_kvth + gb);
        cpa16(sb + OS_BLO + sw, g_kvtl + gb);
    }
    CP_COMMIT();
    CP_WAIT(0);
    __syncthreads();

    float acc[8][4];
    #pragma unroll
    for (int i = 0; i < 8; i++)
        #pragma unroll
        for (int j = 0; j < 4; j++) acc[i][j] = 0.f;

    #pragma unroll
    for (int k16 = 0; k16 < 4; k16++) {
        uint32_t ah[4], al[4];
        {
            const int r  = lane & 15;
            const int kb = (k16*16 + ((lane >> 4) & 1)*8) * 2;
            uint32_t off = (uint32_t)(wm*16 + r)*128 + kb;
            uint32_t sw = off ^ ((off >> 3) & 0x70);
            ldm_x4(sb + OS_QHI + sw, ah);
            ldm_x4(sb + OS_QLO + sw, al);
        }
        uint32_t bh2[4][4], bl2[4][4];
        {
            const int nn = (lane & 7) + ((lane >> 4) & 1)*8;
            const int kb = (k16*16 + ((lane >> 3) & 1)*8) * 2;
            #pragma unroll
            for (int np = 0; np < 4; np++) {
                uint32_t off = (uint32_t)(np*16 + nn)*128 + kb;
                uint32_t sw = off ^ ((off >> 3) & 0x70);
                ldm_x4(sb + OS_BHI + sw, bh2[np]);
                ldm_x4(sb + OS_BLO + sw, bl2[np]);
            }
        }
        #pragma unroll
        for (int nf = 0; nf < 8; nf++)
            mma16816(acc[nf], ah, &bh2[nf >> 1][(nf & 1)*2]);
        #pragma unroll
        for (int nf = 0; nf < 8; nf++)
            mma16816(acc[nf], ah, &bl2[nf >> 1][(nf & 1)*2]);
        #pragma unroll
        for (int nf = 0; nf < 8; nf++)
            mma16816(acc[nf], al, &bh2[nf >> 1][(nf & 1)*2]);
    }
    __syncthreads();

    float* stg = (float*)sm;                        // [128][68]
    #pragma unroll
    for (int nf = 0; nf < 8; nf++) {
        int row = wm*16 + (lane >> 2);
        int col = nf*8 + (lane & 3)*2;
        stg[row*68 + col]       = acc[nf][0];
        stg[row*68 + col + 1]   = acc[nf][1];
        stg[(row+8)*68 + col]   = acc[nf][2];
        stg[(row+8)*68 + col+1] = acc[nf][3];
    }
    __syncthreads();

    #pragma unroll
    for (int i = 0; i < 8; i++) {
        int slot = tid + i*256;
        int row = slot >> 4, c4 = slot & 15;
        float4 v = *(const float4*)&stg[row*68 + c4*4];
        *(float4*)(g_o + (long)(b*SEQ + mt*128 + row)*INNER + h*DHEAD + c4*4) = v;
    }
}

// =====================================================================
// LayerNorm: g_o fp32 -> bf16 hi/lo into g_xhi/g_xlo (A of GEMM2)
// =====================================================================
__global__ __launch_bounds__(256)
void layernorm_rows(const float* __restrict__ gamma, const float* __restrict__ beta)
{
    const float* p = g_o + (long)blockIdx.x*INNER;
    const int tid = threadIdx.x;

    float4 v = ((const float4*)p)[tid];
    float s  = v.x + v.y + v.z + v.w;
    float sq = v.x*v.x + v.y*v.y + v.z*v.z + v.w*v.w;

    #pragma unroll
    for (int o = 16; o > 0; o >>= 1) {
        s  += __shfl_down_sync(0xffffffffu, s,  o);
        sq += __shfl_down_sync(0xffffffffu, sq, o);
    }
    __shared__ float sh[16];
    __shared__ float mu_s, inv_s;
    int wid = tid >> 5, lane = tid & 31;
    if (lane == 0) { sh[wid] = s; sh[8 + wid] = sq; }
    __syncthreads();
    if (tid == 0) {
        float t = 0.f, tq = 0.f;
        #pragma unroll
        for (int i = 0; i < 8; i++) { t += sh[i]; tq += sh[8+i]; }
        float mu = t * (1.f/INNER);
        float var = tq * (1.f/INNER) - mu*mu;
        mu_s = mu;
        inv_s = rsqrtf(fmaxf(var, 0.f) + LN_EPS);
    }
    __syncthreads();

    float mu = mu_s, inv = inv_s;
    float4 g = ((const float4*)gamma)[tid];
    float4 bt = ((const float4*)beta)[tid];
    float f0 = (v.x - mu)*inv*g.x + bt.x;
    float f1 = (v.y - mu)*inv*g.y + bt.y;
    float f2 = (v.z - mu)*inv*g.z + bt.z;
    float f3 = (v.w - mu)*inv*g.w + bt.w;

    __nv_bfloat16 h0,h1,h2,h3,l0,l1,l2,l3;
    split1(f0,h0,l0); split1(f1,h1,l1); split1(f2,h2,l2); split1(f3,h3,l3);
    long i = (long)blockIdx.x*256 + tid;
    ((uint2*)g_xhi)[i] = make_uint2(pack2(h0,h1), pack2(h2,h3));
    ((uint2*)g_xlo)[i] = make_uint2(pack2(l0,l1), pack2(l2,l3));
}

// =====================================================================
// launcher
// =====================================================================
extern "C" void kernel_launch(void* const* d_in, const int* in_sizes, int n_in,
                              void* d_out, int out_size)
{
    const float* x     = (const float*)d_in[0];
    const float* w_qkv = (const float*)d_in[1];
    const float* gamma = (const float*)d_in[2];
    const float* beta  = (const float*)d_in[3];
    const float* w_out = (const float*)d_in[4];
    const float* b_out = (const float*)d_in[5];
    float* out = (float*)d_out;

    cudaFuncSetAttribute(mma_gemm, cudaFuncAttributeMaxDynamicSharedMemorySize, GEMM_SMEM);

    cvt_split<<<MROWS*DIM/1024, 256>>>(x);
    cvt_split_trans<<<dim3(QKVN/32, DIM/32), 256>>>(w_qkv, QKVN, 0);
    cvt_split_trans<<<dim3(DIM/32,  DIM/32), 256>>>(w_out,  DIM, 1);

    // 1: qkv = x @ w_qkv + relu -> q/k/v bf16 hi/lo
    mma_gemm<<<dim3(QKVN/128, MROWS/128), 256, GEMM_SMEM>>>(nullptr, nullptr, 0);
    // 2-3: kv = relu(k)^T v (tensor MMA) -> kv^T hi/lo
    kv_partial<<<512, 256>>>();
    kv_reduce<<<1024, 256>>>();
    // 4: o = q @ kv  (tensor, bf16x3)
    o_mma<<<2048, 256>>>();
    // 5: LayerNorm -> bf16 hi/lo
    layernorm_rows<<<MROWS, 256>>>(gamma, beta);
    // 6: out = LN(o) @ w_out + b_out
    mma_gemm<<<dim3(DIM/128, MROWS/128), 256, GEMM_SMEM>>>(b_out, out, 1);
}

// round 10
// speedup vs baseline: 1.0232x; 1.0232x over previous
#include <cuda_runtime.h>
#include <cuda_bf16.h>
#include <cstdint>

// ---------------- problem constants ----------------
#define BATCH 4
#define SEQ   4096
#define DIM   1024
#define HEADS 16
#define DHEAD 64
#define INNER 1024
#define MROWS (BATCH*SEQ)   // 16384
#define QKVN  (3*INNER)     // 3072
#define LN_EPS 1e-5f

// ---------------- scratch (device globals; no allocs allowed) ----------------
__device__ float g_kvp[64*8*64*64];            // kv split partials (fp32)
__device__ float g_o[MROWS*INNER];             // attention out (fp32), LN reads

// bf16 hi/lo operand storage
__device__ __nv_bfloat16 g_xhi[MROWS*DIM];     // A of GEMM1 (x) and GEMM2 (LN out)
__device__ __nv_bfloat16 g_xlo[MROWS*DIM];
__device__ __nv_bfloat16 g_w1hi[QKVN*DIM];     // w_qkv^T [N][K]
__device__ __nv_bfloat16 g_w1lo[QKVN*DIM];
__device__ __nv_bfloat16 g_w2hi[DIM*DIM];      // w_out^T [N][K]
__device__ __nv_bfloat16 g_w2lo[DIM*DIM];
__device__ __nv_bfloat16 g_qh[BATCH*HEADS*SEQ*DHEAD];
__device__ __nv_bfloat16 g_ql[BATCH*HEADS*SEQ*DHEAD];
__device__ __nv_bfloat16 g_kh[BATCH*HEADS*SEQ*DHEAD];
__device__ __nv_bfloat16 g_kl[BATCH*HEADS*SEQ*DHEAD];
__device__ __nv_bfloat16 g_vh[BATCH*HEADS*SEQ*DHEAD];
__device__ __nv_bfloat16 g_vl[BATCH*HEADS*SEQ*DHEAD];
__device__ __nv_bfloat16 g_kvth[64*64*64];     // kv^T hi/lo  [bh][d][m]
__device__ __nv_bfloat16 g_kvtl[64*64*64];

// =====================================================================
// helpers
// =====================================================================
__device__ __forceinline__ uint32_t smem_u32(const void* p) {
    uint32_t a;
    asm("{ .reg .u64 t; cvta.to.shared.u64 t, %1; cvt.u32.u64 %0, t; }"
        : "=r"(a) : "l"(p));
    return a;
}

__device__ __forceinline__ void cpa16(uint32_t s, const void* g) {
    asm volatile("cp.async.cg.shared.global [%0], [%1], 16;"
                 :: "r"(s), "l"(__cvta_generic_to_global(g)) : "memory");
}
#define CP_COMMIT() asm volatile("cp.async.commit_group;" ::: "memory")
#define CP_WAIT(n)  asm volatile("cp.async.wait_group %0;" :: "n"(n) : "memory")

__device__ __forceinline__ void ldm_x4(uint32_t addr, uint32_t* r) {
    asm volatile("ldmatrix.sync.aligned.m8n8.x4.shared.b16 {%0,%1,%2,%3}, [%4];"
        : "=r"(r[0]), "=r"(r[1]), "=r"(r[2]), "=r"(r[3]) : "r"(addr));
}

__device__ __forceinline__ void mma16816(float* d, const uint32_t* a, const uint32_t* b) {
    asm volatile("mma.sync.aligned.m16n8k16.row.col.f32.bf16.bf16.f32 "
        "{%0,%1,%2,%3}, {%4,%5,%6,%7}, {%8,%9}, {%0,%1,%2,%3};"
        : "+f"(d[0]), "+f"(d[1]), "+f"(d[2]), "+f"(d[3])
        : "r"(a[0]), "r"(a[1]), "r"(a[2]), "r"(a[3]), "r"(b[0]), "r"(b[1]));
}

__device__ __forceinline__ void split1(float f, __nv_bfloat16& h, __nv_bfloat16& l) {
    h = __float2bfloat16(f);
    l = __float2bfloat16(f - __bfloat162float(h));
}

__device__ __forceinline__ uint32_t pack2(__nv_bfloat16 a, __nv_bfloat16 b) {
    __nv_bfloat162 t = __halves2bfloat162(a, b);
    return *reinterpret_cast<uint32_t*>(&t);
}

__device__ __forceinline__ void rec4(uint2 h, uint2 l, float* o) {
    __nv_bfloat162 h0 = *reinterpret_cast<__nv_bfloat162*>(&h.x);
    __nv_bfloat162 h1 = *reinterpret_cast<__nv_bfloat162*>(&h.y);
    __nv_bfloat162 l0 = *reinterpret_cast<__nv_bfloat162*>(&l.x);
    __nv_bfloat162 l1 = *reinterpret_cast<__nv_bfloat162*>(&l.y);
    o[0] = __low2float(h0)  + __low2float(l0);
    o[1] = __high2float(h0) + __high2float(l0);
    o[2] = __low2float(h1)  + __low2float(l1);
    o[3] = __high2float(h1) + __high2float(l1);
}

// =====================================================================
// fused conversion kernel: one launch covers x, w_qkv^T, w_out^T
//   blocks [0, NBX)                     : x -> g_xhi/g_xlo (elementwise)
//   blocks [NBX, NBX+96*32)             : w_qkv transpose-split
//   blocks [NBX+96*32, NBX+96*32+32*32) : w_out transpose-split
// =====================================================================
#define NBX (MROWS*DIM/1024)   // 16384
#define NB1 (96*32)            // 3072
#define NB2 (32*32)            // 1024

__global__ __launch_bounds__(256)
void cvt_all(const float* __restrict__ x,
             const float* __restrict__ w1,
             const float* __restrict__ w2)
{
    const int tid = threadIdx.x;
    int blk = blockIdx.x;

    if (blk < NBX) {
        long i = (long)blk*256 + tid;
        float4 v = ((const float4*)x)[i];
        __nv_bfloat16 h0,h1,h2,h3,l0,l1,l2,l3;
        split1(v.x,h0,l0); split1(v.y,h1,l1); split1(v.z,h2,l2); split1(v.w,h3,l3);
        ((uint2*)g_xhi)[i] = make_uint2(pack2(h0,h1), pack2(h2,h3));
        ((uint2*)g_xlo)[i] = make_uint2(pack2(l0,l1), pack2(l2,l3));
        return;
    }
    blk -= NBX;

    const float* in;
    __nv_bfloat16 *hi, *lo;
    int N, bx;
    if (blk < NB1) { in = w1; hi = g_w1hi; lo = g_w1lo; N = QKVN; bx = blk; }
    else           { in = w2; hi = g_w2hi; lo = g_w2lo; N = DIM;  bx = blk - NB1; }

    __shared__ float t[32][33];
    const int nblk_n = N / 32;
    const int n0 = (bx % nblk_n) * 32;
    const int k0 = (bx / nblk_n) * 32;

    #pragma unroll
    for (int i = 0; i < 4; i++) {
        int r = (tid >> 5) + i*8, c = tid & 31;
        t[r][c] = in[(long)(k0+r)*N + n0 + c];
    }
    __syncthreads();
    #pragma unroll
    for (int i = 0; i < 4; i++) {
        int a = (tid >> 5) + i*8;
        int b = tid & 31;
        float f = t[b][a];
        __nv_bfloat16 h, l;
        split1(f, h, l);
        hi[(long)(n0+a)*DIM + k0 + b] = h;
        lo[(long)(n0+a)*DIM + k0 + b] = l;
    }
}

// =====================================================================
// bf16x3 mma.sync GEMM (R8): CTA 128x128, warp 64x32, K-chunk 64,
//   3-stage cp.async, term-outermost MMA order
// =====================================================================
#define ST_AHI 0
#define ST_ALO 16384
#define ST_BHI 32768
#define ST_BLO 49152
#define ST_SZ  65536
#define GEMM_SMEM (3*ST_SZ)

__global__ __launch_bounds__(256, 1)
void mma_gemm(const float* __restrict__ bias, float* __restrict__ Cout, int mode)
{
    extern __shared__ char smem[];
    const uint32_t sb = smem_u32(smem);
    const int tid  = threadIdx.x;
    const int lane = tid & 31, wid = tid >> 5;
    const int wm = wid >> 2, wn = wid & 3;          // 2 x 4 warps, 64x32 each
    const int m0 = blockIdx.y * 128;
    const int n0 = blockIdx.x * 128;

    const __nv_bfloat16* Ahi = g_xhi;
    const __nv_bfloat16* Alo = g_xlo;
    const __nv_bfloat16* Bhi = mode ? g_w2hi : g_w1hi;
    const __nv_bfloat16* Blo = mode ? g_w2lo : g_w1lo;

    auto issue = [&](int chunk, int buf) {
        const uint32_t so = sb + buf*ST_SZ;
        const int kofs = chunk * 64;
        #pragma unroll
        for (int i = 0; i < 4; i++) {
            int cid = tid + i*256;
            int row = cid >> 3, c16 = cid & 7;
            uint32_t off = row*128 + c16*16;
            uint32_t sw = off ^ ((off >> 3) & 0x70);
            long ga = (long)(m0 + row)*DIM + kofs + c16*8;
            long gb = (long)(n0 + row)*DIM + kofs + c16*8;
            cpa16(so + ST_AHI + sw, Ahi + ga);
            cpa16(so + ST_ALO + sw, Alo + ga);
            cpa16(so + ST_BHI + sw, Bhi + gb);
            cpa16(so + ST_BLO + sw, Blo + gb);
        }
        CP_COMMIT();
    };

    const int ra  = lane & 15;
    const int kba = ((lane >> 4) & 1) * 16;
    const int nnb = (lane & 7) + ((lane >> 4) & 1)*8;
    const int kbb = ((lane >> 3) & 1) * 16;

    float acc[4][4][4];
    #pragma unroll
    for (int a = 0; a < 4; a++)
        #pragma unroll
        for (int b = 0; b < 4; b++)
            #pragma unroll
            for (int d = 0; d < 4; d++) acc[a][b][d] = 0.f;

    issue(0, 0); issue(1, 1);

    int buf = 0, nbuf = 2;
    #pragma unroll 1
    for (int c = 0; c < 16; c++) {
        if (c < 15) { CP_WAIT(1); } else { CP_WAIT(0); }
        __syncthreads();
        if (c + 2 < 16) issue(c + 2, nbuf);

        const uint32_t so = sb + buf*ST_SZ;

        #pragma unroll
        for (int k16 = 0; k16 < 4; k16++) {
            uint32_t ah[4][4], al[4][4], bh2[2][4], bl2[2][4];
            {
                const int ka = k16*32 + kba;
                #pragma unroll
                for (int mf = 0; mf < 4; mf++) {
                    uint32_t off = (uint32_t)(wm*64 + mf*16 + ra)*128 + ka;
                    uint32_t sw = off ^ ((off >> 3) & 0x70);
                    ldm_x4(so + ST_AHI + sw, ah[mf]);
                    ldm_x4(so + ST_ALO + sw, al[mf]);
                }
            }
            {
                const int kb = k16*32 + kbb;
                #pragma unroll
                for (int np = 0; np < 2; np++) {
                    uint32_t off = (uint32_t)(wn*32 + np*16 + nnb)*128 + kb;
                    uint32_t sw = off ^ ((off >> 3) & 0x70);
                    ldm_x4(so + ST_BHI + sw, bh2[np]);
                    ldm_x4(so + ST_BLO + sw, bl2[np]);
                }
            }
            #pragma unroll
            for (int mf = 0; mf < 4; mf++)
                #pragma unroll
                for (int nf = 0; nf < 4; nf++)
                    mma16816(acc[mf][nf], ah[mf], &bh2[nf >> 1][(nf & 1)*2]);
            #pragma unroll
            for (int mf = 0; mf < 4; mf++)
                #pragma unroll
                for (int nf = 0; nf < 4; nf++)
                    mma16816(acc[mf][nf], ah[mf], &bl2[nf >> 1][(nf & 1)*2]);
            #pragma unroll
            for (int mf = 0; mf < 4; mf++)
                #pragma unroll
                for (int nf = 0; nf < 4; nf++)
                    mma16816(acc[mf][nf], al[mf], &bh2[nf >> 1][(nf & 1)*2]);
        }
        buf = (buf == 2) ? 0 : buf + 1;
        nbuf = (nbuf == 2) ? 0 : nbuf + 1;
    }
    __syncthreads();

    // ---- epilogue: stage fp32 in smem, coalesced out ----
    float* stg = (float*)smem;                      // [128][132]
    #pragma unroll
    for (int mf = 0; mf < 4; mf++)
        #pragma unroll
        for (int nf = 0; nf < 4; nf++) {
            int row = wm*64 + mf*16 + (lane >> 2);
            int col = wn*32 + nf*8 + (lane & 3)*2;
            stg[row*132 + col]       = acc[mf][nf][0];
            stg[row*132 + col + 1]   = acc[mf][nf][1];
            stg[(row+8)*132 + col]   = acc[mf][nf][2];
            stg[(row+8)*132 + col+1] = acc[mf][nf][3];
        }
    __syncthreads();

    #pragma unroll 1
    for (int i = 0; i < 16; i++) {
        int slot = tid + i*256;
        int row = slot >> 5, c4 = slot & 31;
        float4 v = *(const float4*)&stg[row*132 + c4*4];
        int gm = m0 + row;
        int gn = n0 + c4*4;
        if (mode == 0) {
            int part = gn >> 10;
            int inner = gn & 1023;
            int h = inner >> 6, d = inner & 63;
            int b = gm >> 12, s = gm & 4095;
            long dst = (((long)(b*16 + h))*4096 + s)*64 + d;
            if (part != 2) {
                v.x = fmaxf(v.x, 0.f); v.y = fmaxf(v.y, 0.f);
                v.z = fmaxf(v.z, 0.f); v.w = fmaxf(v.w, 0.f);
            }
            __nv_bfloat16 h0,h1,h2,h3,l0,l1,l2,l3;
            split1(v.x,h0,l0); split1(v.y,h1,l1); split1(v.z,h2,l2); split1(v.w,h3,l3);
            uint2 uh = make_uint2(pack2(h0,h1), pack2(h2,h3));
            uint2 ul = make_uint2(pack2(l0,l1), pack2(l2,l3));
            if (part == 0)      { *(uint2*)(g_qh+dst) = uh; *(uint2*)(g_ql+dst) = ul; }
            else if (part == 1) { *(uint2*)(g_kh+dst) = uh; *(uint2*)(g_kl+dst) = ul; }
            else                { *(uint2*)(g_vh+dst) = uh; *(uint2*)(g_vl+dst) = ul; }
        } else {
            float4 bs = *(const float4*)(bias + gn);
            v.x += bs.x; v.y += bs.y; v.z += bs.z; v.w += bs.w;
            *(float4*)(Cout + (long)gm*DIM + gn) = v;
        }
    }
}

// =====================================================================
// kv partials: fp32 FFMA on reconstructed k,v (R8 version — measured best)
// =====================================================================
__global__ __launch_bounds__(256)
void kv_partial()
{
    const int bh = blockIdx.x >> 3;
    const int split = blockIdx.x & 7;
    __shared__ float Ks[32][64];
    __shared__ float Vs[32][64];

    const int tid = threadIdx.x;
    const int tm = (tid >> 4) << 2;
    const int tn = (tid & 15) << 2;
    float acc[4][4] = {{0.f}};

    const long base = ((long)bh*SEQ + split*512)*DHEAD;

    for (int n0 = 0; n0 < 512; n0 += 32) {
        #pragma unroll
        for (int r = 0; r < 2; r++) {
            int idx = tid + r*256;
            int row = idx >> 4;
            int col = (idx & 15) << 2;
            long a = base + (long)(n0+row)*DHEAD + col;
            uint2 kh = *(const uint2*)(g_kh+a), kl = *(const uint2*)(g_kl+a);
            uint2 vh = *(const uint2*)(g_vh+a), vl = *(const uint2*)(g_vl+a);
            rec4(kh, kl, &Ks[row][col]);
            rec4(vh, vl, &Vs[row][col]);
        }
        __syncthreads();
        #pragma unroll
        for (int nn = 0; nn < 32; nn++) {
            float4 a = *(const float4*)&Ks[nn][tm];
            float4 b = *(const float4*)&Vs[nn][tn];
            float av[4] = {a.x,a.y,a.z,a.w};
            float bv[4] = {b.x,b.y,b.z,b.w};
            #pragma unroll
            for (int i = 0; i < 4; i++)
                #pragma unroll
                for (int j = 0; j < 4; j++)
                    acc[i][j] = fmaf(av[i], bv[j], acc[i][j]);
        }
        __syncthreads();
    }

    float* dst = g_kvp + (long)blockIdx.x*4096;
    #pragma unroll
    for (int i = 0; i < 4; i++)
        #pragma unroll
        for (int j = 0; j < 4; j++)
            dst[(tm+i)*64 + tn + j] = acc[i][j];
}

__global__ void kv_reduce()
{
    int idx = blockIdx.x*256 + threadIdx.x;
    int bh = idx >> 12;
    int rem = idx & 4095;
    int m = rem >> 6, d = rem & 63;
    float s = 0.f;
    #pragma unroll
    for (int sp = 0; sp < 8; sp++)
        s += g_kvp[((long)(bh*8 + sp))*4096 + rem];
    __nv_bfloat16 h, l;
    split1(s, h, l);
    g_kvth[(long)bh*4096 + d*64 + m] = h;
    g_kvtl[(long)bh*4096 + d*64 + m] = l;
}

// =====================================================================
// o = q @ kv per (b,h): bf16x3 MMA, M=128 N=64 K=64
// =====================================================================
#define OS_QHI 0
#define OS_QLO 16384
#define OS_BHI 32768
#define OS_BLO 40960

__global__ __launch_bounds__(256)
void o_mma()
{
    __shared__ char sm[49152];
    const uint32_t sb = smem_u32(sm);
    const int tid = threadIdx.x;
    const int lane = tid & 31, wm = tid >> 5;       // 8 warps x (16m x 64n)
    const int bh = blockIdx.x >> 5;
    const int mt = blockIdx.x & 31;
    const int b = bh >> 4, h = bh & 15;

    const long qbase = ((long)bh*SEQ + mt*128)*DHEAD;
    #pragma unroll
    for (int i = 0; i < 4; i++) {
        int cid = tid + i*256;
        int row = cid >> 3, c16 = cid & 7;
        uint32_t off = row*128 + c16*16;
        uint32_t sw = off ^ ((off >> 3) & 0x70);
        long ga = qbase + (long)row*DHEAD + c16*8;
        cpa16(sb + OS_QHI + sw, g_qh + ga);
        cpa16(sb + OS_QLO + sw, g_ql + ga);
    }
    #pragma unroll
    for (int i = 0; i < 2; i++) {
        int cid = tid + i*256;
        int row = cid >> 3, c16 = cid & 7;
        uint32_t off = row*128 + c16*16;
        uint32_t sw = off ^ ((off >> 3) & 0x70);
        long gb = (long)bh*4096 + row*64 + c16*8;
        cpa16(sb + OS_BHI + sw, g_kvth + gb);
        cpa16(sb + OS_BLO + sw, g_kvtl + gb);
    }
    CP_COMMIT();
    CP_WAIT(0);
    __syncthreads();

    float acc[8][4];
    #pragma unroll
    for (int i = 0; i < 8; i++)
        #pragma unroll
        for (int j = 0; j < 4; j++) acc[i][j] = 0.f;

    #pragma unroll
    for (int k16 = 0; k16 < 4; k16++) {
        uint32_t ah[4], al[4];
        {
            const int r  = lane & 15;
            const int kb = (k16*16 + ((lane >> 4) & 1)*8) * 2;
            uint32_t off = (uint32_t)(wm*16 + r)*128 + kb;
            uint32_t sw = off ^ ((off >> 3) & 0x70);
            ldm_x4(sb + OS_QHI + sw, ah);
            ldm_x4(sb + OS_QLO + sw, al);
        }
        uint32_t bh2[4][4], bl2[4][4];
        {
            const int nn = (lane & 7) + ((lane >> 4) & 1)*8;
            const int kb = (k16*16 + ((lane >> 3) & 1)*8) * 2;
            #pragma unroll
            for (int np = 0; np < 4; np++) {
                uint32_t off = (uint32_t)(np*16 + nn)*128 + kb;
                uint32_t sw = off ^ ((off >> 3) & 0x70);
                ldm_x4(sb + OS_BHI + sw, bh2[np]);
                ldm_x4(sb + OS_BLO + sw, bl2[np]);
            }
        }
        #pragma unroll
        for (int nf = 0; nf < 8; nf++)
            mma16816(acc[nf], ah, &bh2[nf >> 1][(nf & 1)*2]);
        #pragma unroll
        for (int nf = 0; nf < 8; nf++)
            mma16816(acc[nf], ah, &bl2[nf >> 1][(nf & 1)*2]);
        #pragma unroll
        for (int nf = 0; nf < 8; nf++)
            mma16816(acc[nf], al, &bh2[nf >> 1][(nf & 1)*2]);
    }
    __syncthreads();

    float* stg = (float*)sm;                        // [128][68]
    #pragma unroll
    for (int nf = 0; nf < 8; nf++) {
        int row = wm*16 + (lane >> 2);
        int col = nf*8 + (lane & 3)*2;
        stg[row*68 + col]       = acc[nf][0];
        stg[row*68 + col + 1]   = acc[nf][1];
        stg[(row+8)*68 + col]   = acc[nf][2];
        stg[(row+8)*68 + col+1] = acc[nf][3];
    }
    __syncthreads();

    #pragma unroll
    for (int i = 0; i < 8; i++) {
        int slot = tid + i*256;
        int row = slot >> 4, c4 = slot & 15;
        float4 v = *(const float4*)&stg[row*68 + c4*4];
        *(float4*)(g_o + (long)(b*SEQ + mt*128 + row)*INNER + h*DHEAD + c4*4) = v;
    }
}

// =====================================================================
// LayerNorm: g_o fp32 -> bf16 hi/lo into g_xhi/g_xlo (A of GEMM2)
// =====================================================================
__global__ __launch_bounds__(256)
void layernorm_rows(const float* __restrict__ gamma, const float* __restrict__ beta)
{
    const float* p = g_o + (long)blockIdx.x*INNER;
    const int tid = threadIdx.x;

    float4 v = ((const float4*)p)[tid];
    float s  = v.x + v.y + v.z + v.w;
    float sq = v.x*v.x + v.y*v.y + v.z*v.z + v.w*v.w;

    #pragma unroll
    for (int o = 16; o > 0; o >>= 1) {
        s  += __shfl_down_sync(0xffffffffu, s,  o);
        sq += __shfl_down_sync(0xffffffffu, sq, o);
    }
    __shared__ float sh[16];
    __shared__ float mu_s, inv_s;
    int wid = tid >> 5, lane = tid & 31;
    if (lane == 0) { sh[wid] = s; sh[8 + wid] = sq; }
    __syncthreads();
    if (tid == 0) {
        float t = 0.f, tq = 0.f;
        #pragma unroll
        for (int i = 0; i < 8; i++) { t += sh[i]; tq += sh[8+i]; }
        float mu = t * (1.f/INNER);
        float var = tq * (1.f/INNER) - mu*mu;
        mu_s = mu;
        inv_s = rsqrtf(fmaxf(var, 0.f) + LN_EPS);
    }
    __syncthreads();

    float mu = mu_s, inv = inv_s;
    float4 g = ((const float4*)gamma)[tid];
    float4 bt = ((const float4*)beta)[tid];
    float f0 = (v.x - mu)*inv*g.x + bt.x;
    float f1 = (v.y - mu)*inv*g.y + bt.y;
    float f2 = (v.z - mu)*inv*g.z + bt.z;
    float f3 = (v.w - mu)*inv*g.w + bt.w;

    __nv_bfloat16 h0,h1,h2,h3,l0,l1,l2,l3;
    split1(f0,h0,l0); split1(f1,h1,l1); split1(f2,h2,l2); split1(f3,h3,l3);
    long i = (long)blockIdx.x*256 + tid;
    ((uint2*)g_xhi)[i] = make_uint2(pack2(h0,h1), pack2(h2,h3));
    ((uint2*)g_xlo)[i] = make_uint2(pack2(l0,l1), pack2(l2,l3));
}

// =====================================================================
// launcher
// =====================================================================
extern "C" void kernel_launch(void* const* d_in, const int* in_sizes, int n_in,
                              void* d_out, int out_size)
{
    const float* x     = (const float*)d_in[0];
    const float* w_qkv = (const float*)d_in[1];
    const float* gamma = (const float*)d_in[2];
    const float* beta  = (const float*)d_in[3];
    const float* w_out = (const float*)d_in[4];
    const float* b_out = (const float*)d_in[5];
    float* out = (float*)d_out;

    cudaFuncSetAttribute(mma_gemm, cudaFuncAttributeMaxDynamicSharedMemorySize, GEMM_SMEM);

    // 0: all conversions in one launch
    cvt_all<<<NBX + NB1 + NB2, 256>>>(x, w_qkv, w_out);

    // 1: qkv = x @ w_qkv + relu -> q/k/v bf16 hi/lo
    mma_gemm<<<dim3(QKVN/128, MROWS/128), 256, GEMM_SMEM>>>(nullptr, nullptr, 0);
    // 2-3: kv = relu(k)^T v -> kv^T hi/lo
    kv_partial<<<512, 256>>>();
    kv_reduce<<<1024, 256>>>();
    // 4: o = q @ kv  (tensor, bf16x3)
    o_mma<<<2048, 256>>>();
    // 5: LayerNorm -> bf16 hi/lo
    layernorm_rows<<<MROWS, 256>>>(gamma, beta);
    // 6: out = LN(o) @ w_out + b_out
    mma_gemm<<<dim3(DIM/128, MROWS/128), 256, GEMM_SMEM>>>(b_out, out, 1);
}

// round 11
// speedup vs baseline: 2.1265x; 2.0783x over previous
#include <cuda_runtime.h>
#include <cuda_fp16.h>
#include <cstdint>

// ---------------- problem constants ----------------
#define BATCH 4
#define SEQ   4096
#define DIM   1024
#define HEADS 16
#define DHEAD 64
#define INNER 1024
#define MROWS (BATCH*SEQ)   // 16384
#define QKVN  (3*INNER)     // 3072
#define LN_EPS 1e-5f

// ---------------- scratch (device globals; no allocs allowed) ----------------
__device__ float g_kvp[64*8*64*64];            // kv split partials (fp32)
__device__ float g_o[MROWS*INNER];             // attention out (fp32), LN reads

// fp16 operand storage (single precision term)
__device__ __half g_xh[MROWS*DIM];             // A of GEMM1 (x) and GEMM2 (LN out)
__device__ __half g_w1h[QKVN*DIM];             // w_qkv^T [N][K]
__device__ __half g_w2h[DIM*DIM];              // w_out^T [N][K]
__device__ __half g_qh[BATCH*HEADS*SEQ*DHEAD];
__device__ __half g_kh[BATCH*HEADS*SEQ*DHEAD];
__device__ __half g_vh[BATCH*HEADS*SEQ*DHEAD];
__device__ __half g_kvth[64*64*64];            // kv^T  [bh][d][m]

// =====================================================================
// helpers
// =====================================================================
__device__ __forceinline__ uint32_t smem_u32(const void* p) {
    uint32_t a;
    asm("{ .reg .u64 t; cvta.to.shared.u64 t, %1; cvt.u32.u64 %0, t; }"
        : "=r"(a) : "l"(p));
    return a;
}

__device__ __forceinline__ void cpa16(uint32_t s, const void* g) {
    asm volatile("cp.async.cg.shared.global [%0], [%1], 16;"
                 :: "r"(s), "l"(__cvta_generic_to_global(g)) : "memory");
}
#define CP_COMMIT() asm volatile("cp.async.commit_group;" ::: "memory")
#define CP_WAIT(n)  asm volatile("cp.async.wait_group %0;" :: "n"(n) : "memory")

__device__ __forceinline__ void ldm_x4(uint32_t addr, uint32_t* r) {
    asm volatile("ldmatrix.sync.aligned.m8n8.x4.shared.b16 {%0,%1,%2,%3}, [%4];"
        : "=r"(r[0]), "=r"(r[1]), "=r"(r[2]), "=r"(r[3]) : "r"(addr));
}

__device__ __forceinline__ void mma16816h(float* d, const uint32_t* a, const uint32_t* b) {
    asm volatile("mma.sync.aligned.m16n8k16.row.col.f32.f16.f16.f32 "
        "{%0,%1,%2,%3}, {%4,%5,%6,%7}, {%8,%9}, {%0,%1,%2,%3};"
        : "+f"(d[0]), "+f"(d[1]), "+f"(d[2]), "+f"(d[3])
        : "r"(a[0]), "r"(a[1]), "r"(a[2]), "r"(a[3]), "r"(b[0]), "r"(b[1]));
}

__device__ __forceinline__ uint32_t pack2h(__half a, __half b) {
    __half2 t = __halves2half2(a, b);
    return *reinterpret_cast<uint32_t*>(&t);
}

// =====================================================================
// fused conversion kernel: one launch covers x, w_qkv^T, w_out^T
// =====================================================================
#define NBX (MROWS*DIM/1024)   // 16384
#define NB1 (96*32)            // 3072
#define NB2 (32*32)            // 1024

__global__ __launch_bounds__(256)
void cvt_all(const float* __restrict__ x,
             const float* __restrict__ w1,
             const float* __restrict__ w2)
{
    const int tid = threadIdx.x;
    int blk = blockIdx.x;

    if (blk < NBX) {
        long i = (long)blk*256 + tid;
        float4 v = ((const float4*)x)[i];
        ((uint2*)g_xh)[i] = make_uint2(
            pack2h(__float2half_rn(v.x), __float2half_rn(v.y)),
            pack2h(__float2half_rn(v.z), __float2half_rn(v.w)));
        return;
    }
    blk -= NBX;

    const float* in;
    __half* hi;
    int N, bx;
    if (blk < NB1) { in = w1; hi = g_w1h; N = QKVN; bx = blk; }
    else           { in = w2; hi = g_w2h; N = DIM;  bx = blk - NB1; }

    __shared__ float t[32][33];
    const int nblk_n = N / 32;
    const int n0 = (bx % nblk_n) * 32;
    const int k0 = (bx / nblk_n) * 32;

    #pragma unroll
    for (int i = 0; i < 4; i++) {
        int r = (tid >> 5) + i*8, c = tid & 31;
        t[r][c] = in[(long)(k0+r)*N + n0 + c];
    }
    __syncthreads();
    #pragma unroll
    for (int i = 0; i < 4; i++) {
        int a = (tid >> 5) + i*8;
        int b = tid & 31;
        hi[(long)(n0+a)*DIM + k0 + b] = __float2half_rn(t[b][a]);
    }
}

// =====================================================================
// fp16 single-term mma.sync GEMM: CTA 128x256, warp 64x64 (2x4 warps),
//   K-chunk 64, 3-stage cp.async, MMA:ldmatrix = 4:1
//   mode 0: relu + q/k/v fp16 scatter   (B = w1, Nall=3072)
//   mode 1: +bias, fp32 out row-major   (B = w2, Nall=1024)
// =====================================================================
#define ST_A 0
#define ST_B 16384
#define ST_SZ 49152
#define GEMM_SMEM (3*ST_SZ)    // 147456; epilogue stage 128*260*4=133120 fits

__global__ __launch_bounds__(256, 1)
void mma_gemm(const float* __restrict__ bias, float* __restrict__ Cout, int mode)
{
    extern __shared__ char smem[];
    const uint32_t sb = smem_u32(smem);
    const int tid  = threadIdx.x;
    const int lane = tid & 31, wid = tid >> 5;
    const int wm = wid >> 2, wn = wid & 3;          // 2 x 4 warps, 64x64 each
    const int m0 = blockIdx.y * 128;
    const int n0 = blockIdx.x * 256;

    const __half* Ah = g_xh;
    const __half* Bh = mode ? g_w2h : g_w1h;

    auto issue = [&](int chunk, int buf) {
        const uint32_t so = sb + buf*ST_SZ;
        const int kofs = chunk * 64;
        #pragma unroll
        for (int i = 0; i < 4; i++) {               // A: 1024 chunks (128 rows x 8)
            int cid = tid + i*256;
            int row = cid >> 3, c16 = cid & 7;
            uint32_t off = row*128 + c16*16;
            uint32_t sw = off ^ ((off >> 3) & 0x70);
            cpa16(so + ST_A + sw, Ah + (long)(m0 + row)*DIM + kofs + c16*8);
        }
        #pragma unroll
        for (int i = 0; i < 8; i++) {               // B: 2048 chunks (256 rows x 8)
            int cid = tid + i*256;
            int row = cid >> 3, c16 = cid & 7;
            uint32_t off = row*128 + c16*16;
            uint32_t sw = off ^ ((off >> 3) & 0x70);
            cpa16(so + ST_B + sw, Bh + (long)(n0 + row)*DIM + kofs + c16*8);
        }
        CP_COMMIT();
    };

    const int ra  = lane & 15;
    const int kba = ((lane >> 4) & 1) * 16;        // bytes
    const int nnb = (lane & 7) + ((lane >> 4) & 1)*8;
    const int kbb = ((lane >> 3) & 1) * 16;        // bytes

    float acc[4][8][4];
    #pragma unroll
    for (int a = 0; a < 4; a++)
        #pragma unroll
        for (int b = 0; b < 8; b++)
            #pragma unroll
            for (int d = 0; d < 4; d++) acc[a][b][d] = 0.f;

    issue(0, 0); issue(1, 1);

    int buf = 0, nbuf = 2;
    #pragma unroll 1
    for (int c = 0; c < 16; c++) {
        if (c < 15) { CP_WAIT(1); } else { CP_WAIT(0); }
        __syncthreads();
        if (c + 2 < 16) issue(c + 2, nbuf);

        const uint32_t so = sb + buf*ST_SZ;

        #pragma unroll
        for (int k16 = 0; k16 < 4; k16++) {
            uint32_t ah[4][4], bf[4][4];
            {
                const int ka = k16*32 + kba;
                #pragma unroll
                for (int mf = 0; mf < 4; mf++) {
                    uint32_t off = (uint32_t)(wm*64 + mf*16 + ra)*128 + ka;
                    uint32_t sw = off ^ ((off >> 3) & 0x70);
                    ldm_x4(so + ST_A + sw, ah[mf]);
                }
            }
            {
                const int kb = k16*32 + kbb;
                #pragma unroll
                for (int np = 0; np < 4; np++) {
                    uint32_t off = (uint32_t)(wn*64 + np*16 + nnb)*128 + kb;
                    uint32_t sw = off ^ ((off >> 3) & 0x70);
                    ldm_x4(so + ST_B + sw, bf[np]);
                }
            }
            #pragma unroll
            for (int mf = 0; mf < 4; mf++)
                #pragma unroll
                for (int nf = 0; nf < 8; nf++)
                    mma16816h(acc[mf][nf], ah[mf], &bf[nf >> 1][(nf & 1)*2]);
        }
        buf = (buf == 2) ? 0 : buf + 1;
        nbuf = (nbuf == 2) ? 0 : nbuf + 1;
    }
    __syncthreads();

    // ---- epilogue: stage fp32 in smem, coalesced out ----
    float* stg = (float*)smem;                      // [128][260]
    #pragma unroll
    for (int mf = 0; mf < 4; mf++)
        #pragma unroll
        for (int nf = 0; nf < 8; nf++) {
            int row = wm*64 + mf*16 + (lane >> 2);
            int col = wn*64 + nf*8 + (lane & 3)*2;
            stg[row*260 + col]       = acc[mf][nf][0];
            stg[row*260 + col + 1]   = acc[mf][nf][1];
            stg[(row+8)*260 + col]   = acc[mf][nf][2];
            stg[(row+8)*260 + col+1] = acc[mf][nf][3];
        }
    __syncthreads();

    #pragma unroll 1
    for (int i = 0; i < 32; i++) {
        int slot = tid + i*256;
        int row = slot >> 6, c4 = slot & 63;
        float4 v = *(const float4*)&stg[row*260 + c4*4];
        int gm = m0 + row;
        int gn = n0 + c4*4;
        if (mode == 0) {
            int part = gn >> 10;
            int inner = gn & 1023;
            int h = inner >> 6, d = inner & 63;
            int b = gm >> 12, s = gm & 4095;
            long dst = (((long)(b*16 + h))*4096 + s)*64 + d;
            if (part != 2) {
                v.x = fmaxf(v.x, 0.f); v.y = fmaxf(v.y, 0.f);
                v.z = fmaxf(v.z, 0.f); v.w = fmaxf(v.w, 0.f);
            }
            uint2 uh = make_uint2(
                pack2h(__float2half_rn(v.x), __float2half_rn(v.y)),
                pack2h(__float2half_rn(v.z), __float2half_rn(v.w)));
            if (part == 0)      *(uint2*)(g_qh+dst) = uh;
            else if (part == 1) *(uint2*)(g_kh+dst) = uh;
            else                *(uint2*)(g_vh+dst) = uh;
        } else {
            float4 bs = *(const float4*)(bias + gn);
            v.x += bs.x; v.y += bs.y; v.z += bs.z; v.w += bs.w;
            *(float4*)(Cout + (long)gm*DIM + gn) = v;
        }
    }
}

// =====================================================================
// kv partials: fp32 FFMA on converted fp16 k,v  (half the load traffic)
// =====================================================================
__global__ __launch_bounds__(256)
void kv_partial()
{
    const int bh = blockIdx.x >> 3;
    const int split = blockIdx.x & 7;
    __shared__ float Ks[32][64];
    __shared__ float Vs[32][64];

    const int tid = threadIdx.x;
    const int tm = (tid >> 4) << 2;
    const int tn = (tid & 15) << 2;
    float acc[4][4] = {{0.f}};

    const long base = ((long)bh*SEQ + split*512)*DHEAD;

    for (int n0 = 0; n0 < 512; n0 += 32) {
        #pragma unroll
        for (int r = 0; r < 2; r++) {
            int idx = tid + r*256;
            int row = idx >> 4;
            int col = (idx & 15) << 2;
            long a = base + (long)(n0+row)*DHEAD + col;
            uint2 uk = *(const uint2*)(g_kh+a);
            uint2 uv = *(const uint2*)(g_vh+a);
            __half2 k0 = *reinterpret_cast<__half2*>(&uk.x);
            __half2 k1 = *reinterpret_cast<__half2*>(&uk.y);
            __half2 v0 = *reinterpret_cast<__half2*>(&uv.x);
            __half2 v1 = *reinterpret_cast<__half2*>(&uv.y);
            Ks[row][col+0] = __low2float(k0);  Ks[row][col+1] = __high2float(k0);
            Ks[row][col+2] = __low2float(k1);  Ks[row][col+3] = __high2float(k1);
            Vs[row][col+0] = __low2float(v0);  Vs[row][col+1] = __high2float(v0);
            Vs[row][col+2] = __low2float(v1);  Vs[row][col+3] = __high2float(v1);
        }
        __syncthreads();
        #pragma unroll
        for (int nn = 0; nn < 32; nn++) {
            float4 a = *(const float4*)&Ks[nn][tm];
            float4 b = *(const float4*)&Vs[nn][tn];
            float av[4] = {a.x,a.y,a.z,a.w};
            float bv[4] = {b.x,b.y,b.z,b.w};
            #pragma unroll
            for (int i = 0; i < 4; i++)
                #pragma unroll
                for (int j = 0; j < 4; j++)
                    acc[i][j] = fmaf(av[i], bv[j], acc[i][j]);
        }
        __syncthreads();
    }

    float* dst = g_kvp + (long)blockIdx.x*4096;
    #pragma unroll
    for (int i = 0; i < 4; i++)
        #pragma unroll
        for (int j = 0; j < 4; j++)
            dst[(tm+i)*64 + tn + j] = acc[i][j];
}

__global__ void kv_reduce()
{
    int idx = blockIdx.x*256 + threadIdx.x;
    int bh = idx >> 12;
    int rem = idx & 4095;
    int m = rem >> 6, d = rem & 63;
    float s = 0.f;
    #pragma unroll
    for (int sp = 0; sp < 8; sp++)
        s += g_kvp[((long)(bh*8 + sp))*4096 + rem];
    g_kvth[(long)bh*4096 + d*64 + m] = __float2half_rn(s);
}

// =====================================================================
// o = q @ kv per (b,h): fp16 single-term MMA, M=128 N=64 K=64
// =====================================================================
#define OS_Q 0
#define OS_B 16384

__global__ __launch_bounds__(256)
void o_mma()
{
    __shared__ char sm[34816];      // max(Q 16KB + KVT 8KB, stage 128*68*4=34816)
    const uint32_t sb = smem_u32(sm);
    const int tid = threadIdx.x;
    const int lane = tid & 31, wm = tid >> 5;       // 8 warps x (16m x 64n)
    const int bh = blockIdx.x >> 5;
    const int mt = blockIdx.x & 31;
    const int b = bh >> 4, h = bh & 15;

    const long qbase = ((long)bh*SEQ + mt*128)*DHEAD;
    #pragma unroll
    for (int i = 0; i < 4; i++) {                   // Q: 1024 chunks
        int cid = tid + i*256;
        int row = cid >> 3, c16 = cid & 7;
        uint32_t off = row*128 + c16*16;
        uint32_t sw = off ^ ((off >> 3) & 0x70);
        cpa16(sb + OS_Q + sw, g_qh + qbase + (long)row*DHEAD + c16*8);
    }
    #pragma unroll
    for (int i = 0; i < 2; i++) {                   // KVT: 512 chunks
        int cid = tid + i*256;
        int row = cid >> 3, c16 = cid & 7;
        uint32_t off = row*128 + c16*16;
        uint32_t sw = off ^ ((off >> 3) & 0x70);
        cpa16(sb + OS_B + sw, g_kvth + (long)bh*4096 + row*64 + c16*8);
    }
    CP_COMMIT();
    CP_WAIT(0);
    __syncthreads();

    float acc[8][4];
    #pragma unroll
    for (int i = 0; i < 8; i++)
        #pragma unroll
        for (int j = 0; j < 4; j++) acc[i][j] = 0.f;

    #pragma unroll
    for (int k16 = 0; k16 < 4; k16++) {
        uint32_t ah[4];
        {
            const int r  = lane & 15;
            const int kb = (k16*16 + ((lane >> 4) & 1)*8) * 2;
            uint32_t off = (uint32_t)(wm*16 + r)*128 + kb;
            uint32_t sw = off ^ ((off >> 3) & 0x70);
            ldm_x4(sb + OS_Q + sw, ah);
        }
        uint32_t bf[4][4];
        {
            const int nn = (lane & 7) + ((lane >> 4) & 1)*8;
            const int kb = (k16*16 + ((lane >> 3) & 1)*8) * 2;
            #pragma unroll
            for (int np = 0; np < 4; np++) {
                uint32_t off = (uint32_t)(np*16 + nn)*128 + kb;
                uint32_t sw = off ^ ((off >> 3) & 0x70);
                ldm_x4(sb + OS_B + sw, bf[np]);
            }
        }
        #pragma unroll
        for (int nf = 0; nf < 8; nf++)
            mma16816h(acc[nf], ah, &bf[nf >> 1][(nf & 1)*2]);
    }
    __syncthreads();

    float* stg = (float*)sm;                        // [128][68]
    #pragma unroll
    for (int nf = 0; nf < 8; nf++) {
        int row = wm*16 + (lane >> 2);
        int col = nf*8 + (lane & 3)*2;
        stg[row*68 + col]       = acc[nf][0];
        stg[row*68 + col + 1]   = acc[nf][1];
        stg[(row+8)*68 + col]   = acc[nf][2];
        stg[(row+8)*68 + col+1] = acc[nf][3];
    }
    __syncthreads();

    #pragma unroll
    for (int i = 0; i < 8; i++) {
        int slot = tid + i*256;
        int row = slot >> 4, c4 = slot & 15;
        float4 v = *(const float4*)&stg[row*68 + c4*4];
        *(float4*)(g_o + (long)(b*SEQ + mt*128 + row)*INNER + h*DHEAD + c4*4) = v;
    }
}

// =====================================================================
// LayerNorm: g_o fp32 -> fp16 into g_xh (A of GEMM2)
// =====================================================================
__global__ __launch_bounds__(256)
void layernorm_rows(const float* __restrict__ gamma, const float* __restrict__ beta)
{
    const float* p = g_o + (long)blockIdx.x*INNER;
    const int tid = threadIdx.x;

    float4 v = ((const float4*)p)[tid];
    float s  = v.x + v.y + v.z + v.w;
    float sq = v.x*v.x + v.y*v.y + v.z*v.z + v.w*v.w;

    #pragma unroll
    for (int o = 16; o > 0; o >>= 1) {
        s  += __shfl_down_sync(0xffffffffu, s,  o);
        sq += __shfl_down_sync(0xffffffffu, sq, o);
    }
    __shared__ float sh[16];
    __shared__ float mu_s, inv_s;
    int wid = tid >> 5, lane = tid & 31;
    if (lane == 0) { sh[wid] = s; sh[8 + wid] = sq; }
    __syncthreads();
    if (tid == 0) {
        float t = 0.f, tq = 0.f;
        #pragma unroll
        for (int i = 0; i < 8; i++) { t += sh[i]; tq += sh[8+i]; }
        float mu = t * (1.f/INNER);
        float var = tq * (1.f/INNER) - mu*mu;
        mu_s = mu;
        inv_s = rsqrtf(fmaxf(var, 0.f) + LN_EPS);
    }
    __syncthreads();

    float mu = mu_s, inv = inv_s;
    float4 g = ((const float4*)gamma)[tid];
    float4 bt = ((const float4*)beta)[tid];
    float f0 = (v.x - mu)*inv*g.x + bt.x;
    float f1 = (v.y - mu)*inv*g.y + bt.y;
    float f2 = (v.z - mu)*inv*g.z + bt.z;
    float f3 = (v.w - mu)*inv*g.w + bt.w;

    long i = (long)blockIdx.x*256 + tid;
    ((uint2*)g_xh)[i] = make_uint2(
        pack2h(__float2half_rn(f0), __float2half_rn(f1)),
        pack2h(__float2half_rn(f2), __float2half_rn(f3)));
}

// =====================================================================
// launcher
// =====================================================================
extern "C" void kernel_launch(void* const* d_in, const int* in_sizes, int n_in,
                              void* d_out, int out_size)
{
    const float* x     = (const float*)d_in[0];
    const float* w_qkv = (const float*)d_in[1];
    const float* gamma = (const float*)d_in[2];
    const float* beta  = (const float*)d_in[3];
    const float* w_out = (const float*)d_in[4];
    const float* b_out = (const float*)d_in[5];
    float* out = (float*)d_out;

    cudaFuncSetAttribute(mma_gemm, cudaFuncAttributeMaxDynamicSharedMemorySize, GEMM_SMEM);

    // 0: all conversions in one launch
    cvt_all<<<NBX + NB1 + NB2, 256>>>(x, w_qkv, w_out);

    // 1: qkv = x @ w_qkv + relu -> q/k/v fp16
    mma_gemm<<<dim3(QKVN/256, MROWS/128), 256, GEMM_SMEM>>>(nullptr, nullptr, 0);
    // 2-3: kv = relu(k)^T v -> kv^T fp16
    kv_partial<<<512, 256>>>();
    kv_reduce<<<1024, 256>>>();
    // 4: o = q @ kv  (fp16 tensor)
    o_mma<<<2048, 256>>>();
    // 5: LayerNorm -> fp16
    layernorm_rows<<<MROWS, 256>>>(gamma, beta);
    // 6: out = LN(o) @ w_out + b_out
    mma_gemm<<<dim3(DIM/256, MROWS/128), 256, GEMM_SMEM>>>(b_out, out, 1);
}

// round 12
// speedup vs baseline: 2.4044x; 1.1307x over previous
#include <cuda_runtime.h>
#include <cuda_fp16.h>
#include <cstdint>

// ---------------- problem constants ----------------
#define BATCH 4
#define SEQ   4096
#define DIM   1024
#define HEADS 16
#define DHEAD 64
#define INNER 1024
#define MROWS (BATCH*SEQ)   // 16384
#define QKVN  (3*INNER)     // 3072
#define LN_EPS 1e-5f

// ---------------- scratch (device globals; no allocs allowed) ----------------
__device__ float g_kvp[64*8*64*64];            // kv split partials (fp32)
__device__ float g_o[MROWS*INNER];             // attention out (fp32), LN reads

// fp16 operand storage (single precision term)
__device__ __half g_xh[MROWS*DIM];             // A of GEMM1 (x) and GEMM2 (LN out)
__device__ __half g_w1h[QKVN*DIM];             // w_qkv^T [N][K]
__device__ __half g_w2h[DIM*DIM];              // w_out^T [N][K]
__device__ __half g_qh[BATCH*HEADS*SEQ*DHEAD];
__device__ __half g_kh[BATCH*HEADS*SEQ*DHEAD];
__device__ __half g_vh[BATCH*HEADS*SEQ*DHEAD];
__device__ __half g_kvth[64*64*64];            // kv^T  [bh][d][m]

// =====================================================================
// helpers
// =====================================================================
__device__ __forceinline__ uint32_t smem_u32(const void* p) {
    uint32_t a;
    asm("{ .reg .u64 t; cvta.to.shared.u64 t, %1; cvt.u32.u64 %0, t; }"
        : "=r"(a) : "l"(p));
    return a;
}

__device__ __forceinline__ void cpa16(uint32_t s, const void* g) {
    asm volatile("cp.async.cg.shared.global [%0], [%1], 16;"
                 :: "r"(s), "l"(__cvta_generic_to_global(g)) : "memory");
}
#define CP_COMMIT() asm volatile("cp.async.commit_group;" ::: "memory")
#define CP_WAIT(n)  asm volatile("cp.async.wait_group %0;" :: "n"(n) : "memory")

__device__ __forceinline__ void ldm_x4(uint32_t addr, uint32_t* r) {
    asm volatile("ldmatrix.sync.aligned.m8n8.x4.shared.b16 {%0,%1,%2,%3}, [%4];"
        : "=r"(r[0]), "=r"(r[1]), "=r"(r[2]), "=r"(r[3]) : "r"(addr));
}

__device__ __forceinline__ void mma16816h(float* d, const uint32_t* a, const uint32_t* b) {
    asm volatile("mma.sync.aligned.m16n8k16.row.col.f32.f16.f16.f32 "
        "{%0,%1,%2,%3}, {%4,%5,%6,%7}, {%8,%9}, {%0,%1,%2,%3};"
        : "+f"(d[0]), "+f"(d[1]), "+f"(d[2]), "+f"(d[3])
        : "r"(a[0]), "r"(a[1]), "r"(a[2]), "r"(a[3]), "r"(b[0]), "r"(b[1]));
}

__device__ __forceinline__ uint32_t pack2h(__half a, __half b) {
    __half2 t = __halves2half2(a, b);
    return *reinterpret_cast<uint32_t*>(&t);
}

// =====================================================================
// fused conversion kernel: one launch covers x, w_qkv^T, w_out^T
// =====================================================================
#define NBX (MROWS*DIM/1024)   // 16384
#define NB1 (96*32)            // 3072
#define NB2 (32*32)            // 1024

__global__ __launch_bounds__(256)
void cvt_all(const float* __restrict__ x,
             const float* __restrict__ w1,
             const float* __restrict__ w2)
{
    const int tid = threadIdx.x;
    int blk = blockIdx.x;

    if (blk < NBX) {
        long i = (long)blk*256 + tid;
        float4 v = ((const float4*)x)[i];
        ((uint2*)g_xh)[i] = make_uint2(
            pack2h(__float2half_rn(v.x), __float2half_rn(v.y)),
            pack2h(__float2half_rn(v.z), __float2half_rn(v.w)));
        return;
    }
    blk -= NBX;

    const float* in;
    __half* hi;
    int N, bx;
    if (blk < NB1) { in = w1; hi = g_w1h; N = QKVN; bx = blk; }
    else           { in = w2; hi = g_w2h; N = DIM;  bx = blk - NB1; }

    __shared__ float t[32][33];
    const int nblk_n = N / 32;
    const int n0 = (bx % nblk_n) * 32;
    const int k0 = (bx / nblk_n) * 32;

    #pragma unroll
    for (int i = 0; i < 4; i++) {
        int r = (tid >> 5) + i*8, c = tid & 31;
        t[r][c] = in[(long)(k0+r)*N + n0 + c];
    }
    __syncthreads();
    #pragma unroll
    for (int i = 0; i < 4; i++) {
        int a = (tid >> 5) + i*8;
        int b = tid & 31;
        hi[(long)(n0+a)*DIM + k0 + b] = __float2half_rn(t[b][a]);
    }
}

// =====================================================================
// fp16 single-term mma.sync GEMM: CTA 128x128, warp 64x32 (2x4 warps),
//   K-chunk 64, 3-stage cp.async, *** 2 CTAs/SM *** (acc=64, regs<=128)
//   mode 0: relu + q/k/v fp16 scatter   (B = w1, Nall=3072)
//   mode 1: +bias, fp32 out row-major   (B = w2, Nall=1024)
// =====================================================================
#define ST_A 0
#define ST_B 16384
#define ST_SZ 32768
#define GEMM_SMEM (3*ST_SZ)    // 98304/CTA; 2 CTAs = 192KB <= 228KB
                               // epilogue stage 128*132*4 = 67584 fits

__global__ __launch_bounds__(256, 2)
void mma_gemm(const float* __restrict__ bias, float* __restrict__ Cout, int mode)
{
    extern __shared__ char smem[];
    const uint32_t sb = smem_u32(smem);
    const int tid  = threadIdx.x;
    const int lane = tid & 31, wid = tid >> 5;
    const int wm = wid >> 2, wn = wid & 3;          // 2 x 4 warps, 64x32 each
    const int m0 = blockIdx.y * 128;
    const int n0 = blockIdx.x * 128;

    const __half* Ah = g_xh;
    const __half* Bh = mode ? g_w2h : g_w1h;

    auto issue = [&](int chunk, int buf) {
        const uint32_t so = sb + buf*ST_SZ;
        const int kofs = chunk * 64;
        #pragma unroll
        for (int i = 0; i < 4; i++) {               // A: 1024 16B chunks
            int cid = tid + i*256;
            int row = cid >> 3, c16 = cid & 7;
            uint32_t off = row*128 + c16*16;
            uint32_t sw = off ^ ((off >> 3) & 0x70);
            cpa16(so + ST_A + sw, Ah + (long)(m0 + row)*DIM + kofs + c16*8);
        }
        #pragma unroll
        for (int i = 0; i < 4; i++) {               // B: 1024 16B chunks
            int cid = tid + i*256;
            int row = cid >> 3, c16 = cid & 7;
            uint32_t off = row*128 + c16*16;
            uint32_t sw = off ^ ((off >> 3) & 0x70);
            cpa16(so + ST_B + sw, Bh + (long)(n0 + row)*DIM + kofs + c16*8);
        }
        CP_COMMIT();
    };

    const int ra  = lane & 15;
    const int kba = ((lane >> 4) & 1) * 16;        // bytes
    const int nnb = (lane & 7) + ((lane >> 4) & 1)*8;
    const int kbb = ((lane >> 3) & 1) * 16;        // bytes

    float acc[4][4][4];
    #pragma unroll
    for (int a = 0; a < 4; a++)
        #pragma unroll
        for (int b = 0; b < 4; b++)
            #pragma unroll
            for (int d = 0; d < 4; d++) acc[a][b][d] = 0.f;

    issue(0, 0); issue(1, 1);

    int buf = 0, nbuf = 2;
    #pragma unroll 1
    for (int c = 0; c < 16; c++) {
        if (c < 15) { CP_WAIT(1); } else { CP_WAIT(0); }
        __syncthreads();
        if (c + 2 < 16) issue(c + 2, nbuf);

        const uint32_t so = sb + buf*ST_SZ;

        #pragma unroll
        for (int k16 = 0; k16 < 4; k16++) {
            uint32_t ah[4][4], bf2[2][4];
            {
                const int ka = k16*32 + kba;
                #pragma unroll
                for (int mf = 0; mf < 4; mf++) {
                    uint32_t off = (uint32_t)(wm*64 + mf*16 + ra)*128 + ka;
                    uint32_t sw = off ^ ((off >> 3) & 0x70);
                    ldm_x4(so + ST_A + sw, ah[mf]);
                }
            }
            {
                const int kb = k16*32 + kbb;
                #pragma unroll
                for (int np = 0; np < 2; np++) {
                    uint32_t off = (uint32_t)(wn*32 + np*16 + nnb)*128 + kb;
                    uint32_t sw = off ^ ((off >> 3) & 0x70);
                    ldm_x4(so + ST_B + sw, bf2[np]);
                }
            }
            #pragma unroll
            for (int mf = 0; mf < 4; mf++)
                #pragma unroll
                for (int nf = 0; nf < 4; nf++)
                    mma16816h(acc[mf][nf], ah[mf], &bf2[nf >> 1][(nf & 1)*2]);
        }
        buf = (buf == 2) ? 0 : buf + 1;
        nbuf = (nbuf == 2) ? 0 : nbuf + 1;
    }
    __syncthreads();

    // ---- epilogue: stage fp32 in smem, coalesced out ----
    float* stg = (float*)smem;                      // [128][132]
    #pragma unroll
    for (int mf = 0; mf < 4; mf++)
        #pragma unroll
        for (int nf = 0; nf < 4; nf++) {
            int row = wm*64 + mf*16 + (lane >> 2);
            int col = wn*32 + nf*8 + (lane & 3)*2;
            stg[row*132 + col]       = acc[mf][nf][0];
            stg[row*132 + col + 1]   = acc[mf][nf][1];
            stg[(row+8)*132 + col]   = acc[mf][nf][2];
            stg[(row+8)*132 + col+1] = acc[mf][nf][3];
        }
    __syncthreads();

    #pragma unroll 1
    for (int i = 0; i < 16; i++) {
        int slot = tid + i*256;
        int row = slot >> 5, c4 = slot & 31;
        float4 v = *(const float4*)&stg[row*132 + c4*4];
        int gm = m0 + row;
        int gn = n0 + c4*4;
        if (mode == 0) {
            int part = gn >> 10;
            int inner = gn & 1023;
            int h = inner >> 6, d = inner & 63;
            int b = gm >> 12, s = gm & 4095;
            long dst = (((long)(b*16 + h))*4096 + s)*64 + d;
            if (part != 2) {
                v.x = fmaxf(v.x, 0.f); v.y = fmaxf(v.y, 0.f);
                v.z = fmaxf(v.z, 0.f); v.w = fmaxf(v.w, 0.f);
            }
            uint2 uh = make_uint2(
                pack2h(__float2half_rn(v.x), __float2half_rn(v.y)),
                pack2h(__float2half_rn(v.z), __float2half_rn(v.w)));
            if (part == 0)      *(uint2*)(g_qh+dst) = uh;
            else if (part == 1) *(uint2*)(g_kh+dst) = uh;
            else                *(uint2*)(g_vh+dst) = uh;
        } else {
            float4 bs = *(const float4*)(bias + gn);
            v.x += bs.x; v.y += bs.y; v.z += bs.z; v.w += bs.w;
            *(float4*)(Cout + (long)gm*DIM + gn) = v;
        }
    }
}

// =====================================================================
// kv partials: fp32 FFMA on converted fp16 k,v
// =====================================================================
__global__ __launch_bounds__(256)
void kv_partial()
{
    const int bh = blockIdx.x >> 3;
    const int split = blockIdx.x & 7;
    __shared__ float Ks[32][64];
    __shared__ float Vs[32][64];

    const int tid = threadIdx.x;
    const int tm = (tid >> 4) << 2;
    const int tn = (tid & 15) << 2;
    float acc[4][4] = {{0.f}};

    const long base = ((long)bh*SEQ + split*512)*DHEAD;

    for (int n0 = 0; n0 < 512; n0 += 32) {
        #pragma unroll
        for (int r = 0; r < 2; r++) {
            int idx = tid + r*256;
            int row = idx >> 4;
            int col = (idx & 15) << 2;
            long a = base + (long)(n0+row)*DHEAD + col;
            uint2 uk = *(const uint2*)(g_kh+a);
            uint2 uv = *(const uint2*)(g_vh+a);
            __half2 k0 = *reinterpret_cast<__half2*>(&uk.x);
            __half2 k1 = *reinterpret_cast<__half2*>(&uk.y);
            __half2 v0 = *reinterpret_cast<__half2*>(&uv.x);
            __half2 v1 = *reinterpret_cast<__half2*>(&uv.y);
            Ks[row][col+0] = __low2float(k0);  Ks[row][col+1] = __high2float(k0);
            Ks[row][col+2] = __low2float(k1);  Ks[row][col+3] = __high2float(k1);
            Vs[row][col+0] = __low2float(v0);  Vs[row][col+1] = __high2float(v0);
            Vs[row][col+2] = __low2float(v1);  Vs[row][col+3] = __high2float(v1);
        }
        __syncthreads();
        #pragma unroll
        for (int nn = 0; nn < 32; nn++) {
            float4 a = *(const float4*)&Ks[nn][tm];
            float4 b = *(const float4*)&Vs[nn][tn];
            float av[4] = {a.x,a.y,a.z,a.w};
            float bv[4] = {b.x,b.y,b.z,b.w};
            #pragma unroll
            for (int i = 0; i < 4; i++)
                #pragma unroll
                for (int j = 0; j < 4; j++)
                    acc[i][j] = fmaf(av[i], bv[j], acc[i][j]);
        }
        __syncthreads();
    }

    float* dst = g_kvp + (long)blockIdx.x*4096;
    #pragma unroll
    for (int i = 0; i < 4; i++)
        #pragma unroll
        for (int j = 0; j < 4; j++)
            dst[(tm+i)*64 + tn + j] = acc[i][j];
}

__global__ void kv_reduce()
{
    int idx = blockIdx.x*256 + threadIdx.x;
    int bh = idx >> 12;
    int rem = idx & 4095;
    int m = rem >> 6, d = rem & 63;
    float s = 0.f;
    #pragma unroll
    for (int sp = 0; sp < 8; sp++)
        s += g_kvp[((long)(bh*8 + sp))*4096 + rem];
    g_kvth[(long)bh*4096 + d*64 + m] = __float2half_rn(s);
}

// =====================================================================
// o = q @ kv per (b,h): fp16 single-term MMA, M=128 N=64 K=64
// =====================================================================
#define OS_Q 0
#define OS_B 16384

__global__ __launch_bounds__(256)
void o_mma()
{
    __shared__ char sm[34816];      // max(Q 16KB + KVT 8KB, stage 128*68*4=34816)
    const uint32_t sb = smem_u32(sm);
    const int tid = threadIdx.x;
    const int lane = tid & 31, wm = tid >> 5;       // 8 warps x (16m x 64n)
    const int bh = blockIdx.x >> 5;
    const int mt = blockIdx.x & 31;
    const int b = bh >> 4, h = bh & 15;

    const long qbase = ((long)bh*SEQ + mt*128)*DHEAD;
    #pragma unroll
    for (int i = 0; i < 4; i++) {
        int cid = tid + i*256;
        int row = cid >> 3, c16 = cid & 7;
        uint32_t off = row*128 + c16*16;
        uint32_t sw = off ^ ((off >> 3) & 0x70);
        cpa16(sb + OS_Q + sw, g_qh + qbase + (long)row*DHEAD + c16*8);
    }
    #pragma unroll
    for (int i = 0; i < 2; i++) {
        int cid = tid + i*256;
        int row = cid >> 3, c16 = cid & 7;
        uint32_t off = row*128 + c16*16;
        uint32_t sw = off ^ ((off >> 3) & 0x70);
        cpa16(sb + OS_B + sw, g_kvth + (long)bh*4096 + row*64 + c16*8);
    }
    CP_COMMIT();
    CP_WAIT(0);
    __syncthreads();

    float acc[8][4];
    #pragma unroll
    for (int i = 0; i < 8; i++)
        #pragma unroll
        for (int j = 0; j < 4; j++) acc[i][j] = 0.f;

    #pragma unroll
    for (int k16 = 0; k16 < 4; k16++) {
        uint32_t ah[4];
        {
            const int r  = lane & 15;
            const int kb = (k16*16 + ((lane >> 4) & 1)*8) * 2;
            uint32_t off = (uint32_t)(wm*16 + r)*128 + kb;
            uint32_t sw = off ^ ((off >> 3) & 0x70);
            ldm_x4(sb + OS_Q + sw, ah);
        }
        uint32_t bf[4][4];
        {
            const int nn = (lane & 7) + ((lane >> 4) & 1)*8;
            const int kb = (k16*16 + ((lane >> 3) & 1)*8) * 2;
            #pragma unroll
            for (int np = 0; np < 4; np++) {
                uint32_t off = (uint32_t)(np*16 + nn)*128 + kb;
                uint32_t sw = off ^ ((off >> 3) & 0x70);
                ldm_x4(sb + OS_B + sw, bf[np]);
            }
        }
        #pragma unroll
        for (int nf = 0; nf < 8; nf++)
            mma16816h(acc[nf], ah, &bf[nf >> 1][(nf & 1)*2]);
    }
    __syncthreads();

    float* stg = (float*)sm;                        // [128][68]
    #pragma unroll
    for (int nf = 0; nf < 8; nf++) {
        int row = wm*16 + (lane >> 2);
        int col = nf*8 + (lane & 3)*2;
        stg[row*68 + col]       = acc[nf][0];
        stg[row*68 + col + 1]   = acc[nf][1];
        stg[(row+8)*68 + col]   = acc[nf][2];
        stg[(row+8)*68 + col+1] = acc[nf][3];
    }
    __syncthreads();

    #pragma unroll
    for (int i = 0; i < 8; i++) {
        int slot = tid + i*256;
        int row = slot >> 4, c4 = slot & 15;
        float4 v = *(const float4*)&stg[row*68 + c4*4];
        *(float4*)(g_o + (long)(b*SEQ + mt*128 + row)*INNER + h*DHEAD + c4*4) = v;
    }
}

// =====================================================================
// LayerNorm: g_o fp32 -> fp16 into g_xh (A of GEMM2)
// =====================================================================
__global__ __launch_bounds__(256)
void layernorm_rows(const float* __restrict__ gamma, const float* __restrict__ beta)
{
    const float* p = g_o + (long)blockIdx.x*INNER;
    const int tid = threadIdx.x;

    float4 v = ((const float4*)p)[tid];
    float s  = v.x + v.y + v.z + v.w;
    float sq = v.x*v.x + v.y*v.y + v.z*v.z + v.w*v.w;

    #pragma unroll
    for (int o = 16; o > 0; o >>= 1) {
        s  += __shfl_down_sync(0xffffffffu, s,  o);
        sq += __shfl_down_sync(0xffffffffu, sq, o);
    }
    __shared__ float sh[16];
    __shared__ float mu_s, inv_s;
    int wid = tid >> 5, lane = tid & 31;
    if (lane == 0) { sh[wid] = s; sh[8 + wid] = sq; }
    __syncthreads();
    if (tid == 0) {
        float t = 0.f, tq = 0.f;
        #pragma unroll
        for (int i = 0; i < 8; i++) { t += sh[i]; tq += sh[8+i]; }
        float mu = t * (1.f/INNER);
        float var = tq * (1.f/INNER) - mu*mu;
        mu_s = mu;
        inv_s = rsqrtf(fmaxf(var, 0.f) + LN_EPS);
    }
    __syncthreads();

    float mu = mu_s, inv = inv_s;
    float4 g = ((const float4*)gamma)[tid];
    float4 bt = ((const float4*)beta)[tid];
    float f0 = (v.x - mu)*inv*g.x + bt.x;
    float f1 = (v.y - mu)*inv*g.y + bt.y;
    float f2 = (v.z - mu)*inv*g.z + bt.z;
    float f3 = (v.w - mu)*inv*g.w + bt.w;

    long i = (long)blockIdx.x*256 + tid;
    ((uint2*)g_xh)[i] = make_uint2(
        pack2h(__float2half_rn(f0), __float2half_rn(f1)),
        pack2h(__float2half_rn(f2), __float2half_rn(f3)));
}

// =====================================================================
// launcher
// =====================================================================
extern "C" void kernel_launch(void* const* d_in, const int* in_sizes, int n_in,
                              void* d_out, int out_size)
{
    const float* x     = (const float*)d_in[0];
    const float* w_qkv = (const float*)d_in[1];
    const float* gamma = (const float*)d_in[2];
    const float* beta  = (const float*)d_in[3];
    const float* w_out = (const float*)d_in[4];
    const float* b_out = (const float*)d_in[5];
    float* out = (float*)d_out;

    cudaFuncSetAttribute(mma_gemm, cudaFuncAttributeMaxDynamicSharedMemorySize, GEMM_SMEM);

    // 0: all conversions in one launch
    cvt_all<<<NBX + NB1 + NB2, 256>>>(x, w_qkv, w_out);

    // 1: qkv = x @ w_qkv + relu -> q/k/v fp16
    mma_gemm<<<dim3(QKVN/128, MROWS/128), 256, GEMM_SMEM>>>(nullptr, nullptr, 0);
    // 2-3: kv = relu(k)^T v -> kv^T fp16
    kv_partial<<<512, 256>>>();
    kv_reduce<<<1024, 256>>>();
    // 4: o = q @ kv  (fp16 tensor)
    o_mma<<<2048, 256>>>();
    // 5: LayerNorm -> fp16
    layernorm_rows<<<MROWS, 256>>>(gamma, beta);
    // 6: out = LN(o) @ w_out + b_out
    mma_gemm<<<dim3(DIM/128, MROWS/128), 256, GEMM_SMEM>>>(b_out, out, 1);
}